// round 11
// baseline (speedup 1.0000x reference)
#include <cuda_runtime.h>
#include <cuda_fp16.h>
#include <cstdint>

// ============================================================================
// Tensor-core FIR via baseline mma.sync (HMMA) — compute_103-safe (no tcgen05).
// out[b,t] = sum_{i<kt} krev[i]*u[b,t+i],  krev[i] = kern[kt-1-i]
// Per tile GEMM: D[128 x 64] = U[128 x 256] * T^T,  T[n,k] = krev[k-n]
// fp16 K-split, 2 passes: U*Kh + U*Kl  (error ~2^-11 from U rounding only).
// A: ring of 4 SMEM panels (64 cols, row-major fp16, +8 halves pad).
// B: built once per CTA directly in m16n8k16 fragment order (hi+lo packed).
// ============================================================================

#define TM_M 128
#define TM_N 64
#define TM_K 256
#define NTH  256
#define KS   16            // K / 16
#define NCH  8             // N / 8

#define A_STRIDE 72                             // 64 + 8 halves pad
#define A_PANEL_BYTES (TM_M * A_STRIDE * 2)     // 18432
#define OFF_A 0
#define OFF_B (4 * A_PANEL_BYTES)               // 73728
#define B_BYTES (KS * NCH * 32 * 16)            // 65536
#define SMEM_TOTAL (OFF_B + B_BYTES)            // 139264

__device__ __forceinline__ uint32_t smem_addr(const void* p) {
    uint32_t a;
    asm("{ .reg .u64 t; cvta.to.shared.u64 t, %1; cvt.u32.u64 %0, t; }" : "=r"(a) : "l"(p));
    return a;
}

__device__ __forceinline__ void ldmA(uint32_t* r, uint32_t addr) {
    asm volatile("ldmatrix.sync.aligned.m8n8.x4.shared.b16 {%0,%1,%2,%3}, [%4];"
                 : "=r"(r[0]), "=r"(r[1]), "=r"(r[2]), "=r"(r[3]) : "r"(addr));
}
__device__ __forceinline__ void hmma(float* c, const uint32_t* a, uint32_t b0, uint32_t b1) {
    asm volatile(
        "mma.sync.aligned.m16n8k16.row.col.f32.f16.f16.f32 "
        "{%0,%1,%2,%3}, {%4,%5,%6,%7}, {%8,%9}, {%0,%1,%2,%3};"
        : "+f"(c[0]), "+f"(c[1]), "+f"(c[2]), "+f"(c[3])
        : "r"(a[0]), "r"(a[1]), "r"(a[2]), "r"(a[3]), "r"(b0), "r"(b1));
}
__device__ __forceinline__ uint32_t pkh(__half a, __half b) {
    return (uint32_t)__half_as_ushort(a) | ((uint32_t)__half_as_ushort(b) << 16);
}

__global__ __launch_bounds__(NTH, 1)
void fir_hmma_kernel(const float* __restrict__ u,
                     const float* __restrict__ kern,
                     float* __restrict__ out,
                     int t_out, int t_in, int b_total, int kt,
                     int n_ttiles, int tps)
{
    extern __shared__ char dsm[];
    const uint32_t sbase = smem_addr(dsm);
    const int tid  = threadIdx.x;
    const int wid  = tid >> 5;
    const int lane = tid & 31;
    const long long b0 = (long long)blockIdx.y * TM_M;
    const int tile0 = blockIdx.x * tps;
    const int ntile = min(tps, n_ttiles - tile0);
    const bool al4  = ((t_in & 3) == 0);

    // ---- build B in fragment order (once per CTA) ----
    // Bfrag[ks][nc][lane] = 16B: {kh(k0,k0+1), kh(k0+8,k0+9), kl(...), kl(...)}
    // lane needs B[k][n] for n = nc*8 + lane/4, k = ks*16 + 2*(lane%4) (+1,+8,+9).
    for (int idx = tid; idx < KS * NCH * 32; idx += NTH) {
        int l  = idx & 31;
        int nc = (idx >> 5) & 7;
        int ks = idx >> 8;
        int n  = nc * 8 + (l >> 2);
        int kb = ks * 16 + 2 * (l & 3);
        float v[4];
        #pragma unroll
        for (int q = 0; q < 4; q++) {
            int k = kb + (q & 1) + ((q >> 1) << 3);   // k0, k0+1, k0+8, k0+9
            int i = k - n;
            v[q] = (i >= 0 && i < kt) ? kern[kt - 1 - i] : 0.0f;
        }
        __half h[4], lo[4];
        #pragma unroll
        for (int q = 0; q < 4; q++) {
            h[q]  = __float2half_rn(v[q]);
            lo[q] = __float2half_rn(v[q] - __half2float(h[q]));
        }
        uint4 w;
        w.x = pkh(h[0],  h[1]);  w.y = pkh(h[2],  h[3]);
        w.z = pkh(lo[0], lo[1]); w.w = pkh(lo[2], lo[3]);
        reinterpret_cast<uint4*>(dsm + OFF_B)[idx] = w;
    }

    // ---- A panel staging: 128 rows x 64 cols fp16, row-major stride 72 ----
    auto fill_panel = [&](int p, int c0) {
        char* pb = dsm + OFF_A + p * A_PANEL_BYTES;
        #pragma unroll 2
        for (int f = tid; f < TM_M * 16; f += NTH) {
            int row = f >> 4;
            int cl  = (f & 15) << 2;
            int g   = c0 + cl;
            long long b = b0 + row;
            float4 v = make_float4(0.f, 0.f, 0.f, 0.f);
            if (b < b_total) {
                const float* up = u + b * (long long)t_in + g;
                if (al4 && (g + 3 < t_in)) {
                    v = *(const float4*)up;
                } else {
                    if (g     < t_in) v.x = up[0];
                    if (g + 1 < t_in) v.y = up[1];
                    if (g + 2 < t_in) v.z = up[2];
                    if (g + 3 < t_in) v.w = up[3];
                }
            }
            uint2 hv;
            hv.x = pkh(__float2half_rn(v.x), __float2half_rn(v.y));
            hv.y = pkh(__float2half_rn(v.z), __float2half_rn(v.w));
            *reinterpret_cast<uint2*>(pb + (row * A_STRIDE + cl) * 2) = hv;
        }
    };

    const int m0 = wid * 16;
    // ldmatrix per-lane base: row = m0 + (l&7) + (l&8); col-half offset (l&16)?8:0
    const uint32_t arow = sbase + OFF_A +
        (uint32_t)(((m0 + (lane & 7) + (lane & 8)) * A_STRIDE + ((lane & 16) ? 8 : 0)) * 2);

    int rs = 0;
    for (int s = 0; s < ntile; s++) {
        const int w0 = (tile0 + s) * TM_N;

        if (s == 0) {
            #pragma unroll 1
            for (int p = 0; p < 4; p++) fill_panel(p, w0 + 64 * p);
        } else {
            fill_panel((rs + 3) & 3, w0 + 192);
        }
        __syncthreads();

        float acc[NCH][4];
        #pragma unroll
        for (int nc = 0; nc < NCH; nc++)
            #pragma unroll
            for (int q = 0; q < 4; q++) acc[nc][q] = 0.0f;

        #pragma unroll 1
        for (int ks = 0; ks < KS; ks++) {
            const int p = (rs + (ks >> 2)) & 3;
            uint32_t a[4];
            ldmA(a, arow + (uint32_t)(p * A_PANEL_BYTES + ((ks & 3) * 16) * 2));
            const uint4* bp = reinterpret_cast<const uint4*>(dsm + OFF_B)
                              + (ks * NCH) * 32 + lane;
            #pragma unroll
            for (int nc = 0; nc < NCH; nc++) {
                uint4 bv = bp[nc * 32];
                hmma(acc[nc], a, bv.x, bv.y);   // pass 1: U * Kh
                hmma(acc[nc], a, bv.z, bv.w);   // pass 2: U * Kl
            }
        }

        // ---- epilogue: D frag c0,c1 -> row l/4, cols 2(l%4)+{0,1}; c2,c3 -> row+8
        const long long r0 = b0 + m0 + (lane >> 2);
        #pragma unroll
        for (int nc = 0; nc < NCH; nc++) {
            int col = w0 + nc * 8 + (lane & 3) * 2;
            if (col < t_out) {   // t_out even, col even -> col+1 < t_out too
                if (r0 < b_total)
                    *reinterpret_cast<float2*>(out + r0 * t_out + col) =
                        make_float2(acc[nc][0], acc[nc][1]);
                if (r0 + 8 < b_total)
                    *reinterpret_cast<float2*>(out + (r0 + 8) * t_out + col) =
                        make_float2(acc[nc][2], acc[nc][3]);
            }
        }
        __syncthreads();   // all warps done reading panels before next overwrite
        rs = (rs + 1) & 3;
    }
}

// Generic fallback for unexpected tap counts.
__global__ void fir_generic_kernel(const float* __restrict__ u,
                                   const float* __restrict__ kern,
                                   float* __restrict__ out,
                                   int t_out, int t_in, int kt)
{
    int t = blockIdx.x * blockDim.x + threadIdx.x;
    int row = blockIdx.y;
    if (t >= t_out) return;
    const float* urow = u + (long long)row * t_in;
    float acc = 0.0f;
    for (int i = 0; i < kt; i++)
        acc = fmaf(kern[kt - 1 - i], urow[t + i], acc);
    out[(long long)row * t_out + t] = acc;
}

extern "C" void kernel_launch(void* const* d_in, const int* in_sizes, int n_in,
                              void* d_out, int out_size)
{
    const float* u    = (const float*)d_in[0];
    const float* kern = (const float*)d_in[1];
    float* out        = (float*)d_out;

    const int kt      = in_sizes[1];
    const int b_total = (kt > 1) ? (in_sizes[0] - out_size) / (kt - 1) : 1;
    const int t_out   = out_size / b_total;
    const int t_in    = in_sizes[0] / b_total;

    if (kt >= 1 && kt <= TM_K - TM_N + 1) {
        cudaFuncSetAttribute(fir_hmma_kernel,
                             cudaFuncAttributeMaxDynamicSharedMemorySize, SMEM_TOTAL);
        const int n_btiles = (b_total + TM_M - 1) / TM_M;
        const int n_ttiles = (t_out + TM_N - 1) / TM_N;
        int strips_max = 148 / n_btiles; if (strips_max < 1) strips_max = 1;
        int tps    = (n_ttiles + strips_max - 1) / strips_max;
        int strips = (n_ttiles + tps - 1) / tps;
        dim3 grid(strips, n_btiles);
        fir_hmma_kernel<<<grid, NTH, SMEM_TOTAL>>>(u, kern, out, t_out, t_in,
                                                   b_total, kt, n_ttiles, tps);
    } else {
        dim3 grid((t_out + 255) / 256, b_total);
        fir_generic_kernel<<<grid, 256>>>(u, kern, out, t_out, t_in, kt);
    }
}

// round 12
// speedup vs baseline: 1.9333x; 1.9333x over previous
#include <cuda_runtime.h>
#include <cuda_fp16.h>
#include <cstdint>

// ============================================================================
// Tensor-core FIR via baseline mma.sync (HMMA), software-pipelined.
// out[b,t] = sum_{i<kt} krev[i]*u[b,t+i],  krev[i] = kern[kt-1-i]
// Per tile: D[256 x 64] = U[256 x 256] * T^T,  T[n,k] = krev[k-n]
// fp16 K-split, 2 passes: U*Kh + U*Kl.
// A: ring of 4 SMEM panels (256 rows x 64 cols fp16, stride 72).
// B: built once per CTA in m16n8k16 fragment order (hi+lo packed, 16B/lane).
// Pipeline: prefetch next panel to regs (LDG) before MMA, STS after.
// Warp tile: 32 rows x 32 cols  (mg = wid>>1: 8 groups, ng = wid&1: 4 nc each)
// ============================================================================

#define TM_M 256
#define TM_N 64
#define TM_K 256
#define NTH  512
#define KS   16
#define NCH  8

#define A_STRIDE 72                              // 64 + 8 halves pad
#define A_PANEL_BYTES (TM_M * A_STRIDE * 2)      // 36864
#define OFF_A 0
#define OFF_B (4 * A_PANEL_BYTES)                // 147456
#define B_BYTES (KS * NCH * 32 * 16)             // 65536
#define SMEM_TOTAL (OFF_B + B_BYTES)             // 212992

__device__ __forceinline__ uint32_t smem_addr(const void* p) {
    uint32_t a;
    asm("{ .reg .u64 t; cvta.to.shared.u64 t, %1; cvt.u32.u64 %0, t; }" : "=r"(a) : "l"(p));
    return a;
}
__device__ __forceinline__ void ldmA(uint32_t* r, uint32_t addr) {
    asm volatile("ldmatrix.sync.aligned.m8n8.x4.shared.b16 {%0,%1,%2,%3}, [%4];"
                 : "=r"(r[0]), "=r"(r[1]), "=r"(r[2]), "=r"(r[3]) : "r"(addr));
}
__device__ __forceinline__ void hmma(float* c, const uint32_t* a, uint32_t b0, uint32_t b1) {
    asm volatile(
        "mma.sync.aligned.m16n8k16.row.col.f32.f16.f16.f32 "
        "{%0,%1,%2,%3}, {%4,%5,%6,%7}, {%8,%9}, {%0,%1,%2,%3};"
        : "+f"(c[0]), "+f"(c[1]), "+f"(c[2]), "+f"(c[3])
        : "r"(a[0]), "r"(a[1]), "r"(a[2]), "r"(a[3]), "r"(b0), "r"(b1));
}
__device__ __forceinline__ uint32_t pkh(__half a, __half b) {
    return (uint32_t)__half_as_ushort(a) | ((uint32_t)__half_as_ushort(b) << 16);
}

__global__ __launch_bounds__(NTH, 1)
void fir_hmma_kernel(const float* __restrict__ u,
                     const float* __restrict__ kern,
                     float* __restrict__ out,
                     int t_out, int t_in, int b_total, int kt,
                     int n_ttiles, int tps)
{
    extern __shared__ char dsm[];
    const uint32_t sbase = smem_addr(dsm);
    const int tid  = threadIdx.x;
    const int wid  = tid >> 5;
    const int lane = tid & 31;
    const long long b0 = (long long)blockIdx.y * TM_M;
    const int tile0 = blockIdx.x * tps;
    const int ntile = min(tps, n_ttiles - tile0);
    const bool al4  = ((t_in & 3) == 0);

    // ---- build B in fragment order (once per CTA) ----
    // Bfrag[ks][nc][lane] 16B: {kh(k0,k0+1), kh(k0+8,k0+9), kl(..), kl(..)}
    // lane's n = nc*8 + lane/4, k0 = ks*16 + 2*(lane%4).
    for (int idx = tid; idx < KS * NCH * 32; idx += NTH) {
        int l  = idx & 31;
        int nc = (idx >> 5) & 7;
        int ks = idx >> 8;
        int n  = nc * 8 + (l >> 2);
        int kb = ks * 16 + 2 * (l & 3);
        float v[4];
        #pragma unroll
        for (int q = 0; q < 4; q++) {
            int k = kb + (q & 1) + ((q >> 1) << 3);
            int i = k - n;
            v[q] = (i >= 0 && i < kt) ? kern[kt - 1 - i] : 0.0f;
        }
        __half h[4], lo[4];
        #pragma unroll
        for (int q = 0; q < 4; q++) {
            h[q]  = __float2half_rn(v[q]);
            lo[q] = __float2half_rn(v[q] - __half2float(h[q]));
        }
        uint4 w;
        w.x = pkh(h[0],  h[1]);  w.y = pkh(h[2],  h[3]);
        w.z = pkh(lo[0], lo[1]); w.w = pkh(lo[2], lo[3]);
        reinterpret_cast<uint4*>(dsm + OFF_B)[idx] = w;
    }

    // ---- panel helpers: 256 rows x 16 float4 per panel, 8 float4/thread ----
    float4 pf[8];
    auto ld_pf = [&](int c0) {
        #pragma unroll
        for (int q = 0; q < 8; q++) {
            int f   = tid + q * NTH;
            int row = f >> 4;
            int cl  = (f & 15) << 2;
            int g   = c0 + cl;
            long long b = b0 + row;
            float4 v = make_float4(0.f, 0.f, 0.f, 0.f);
            if (b < b_total) {
                const float* up = u + b * (long long)t_in + g;
                if (al4 && (g + 3 < t_in)) {
                    v = *(const float4*)up;
                } else {
                    if (g     < t_in) v.x = up[0];
                    if (g + 1 < t_in) v.y = up[1];
                    if (g + 2 < t_in) v.z = up[2];
                    if (g + 3 < t_in) v.w = up[3];
                }
            }
            pf[q] = v;
        }
    };
    auto st_pf = [&](int p) {
        char* pb = dsm + OFF_A + p * A_PANEL_BYTES;
        #pragma unroll
        for (int q = 0; q < 8; q++) {
            int f   = tid + q * NTH;
            int row = f >> 4;
            int cl  = (f & 15) << 2;
            uint2 hv;
            hv.x = pkh(__float2half_rn(pf[q].x), __float2half_rn(pf[q].y));
            hv.y = pkh(__float2half_rn(pf[q].z), __float2half_rn(pf[q].w));
            *reinterpret_cast<uint2*>(pb + (row * A_STRIDE + cl) * 2) = hv;
        }
    };

    // ---- warp tiling: 32 rows x 32 cols ----
    const int mg  = wid >> 1;          // 0..7  -> rows mg*32 .. mg*32+31
    const int ng  = wid & 1;           // 0..1  -> nc ng*4 .. ng*4+3
    const int m0  = mg * 32;
    const uint32_t arow0 = sbase + OFF_A +
        (uint32_t)(((m0 + (lane & 7) + (lane & 8)) * A_STRIDE + ((lane & 16) ? 8 : 0)) * 2);
    const uint32_t arow1 = arow0 + (uint32_t)(16 * A_STRIDE * 2);

    // ---- initial fill: panels 0..3 ----
    const int w0f = tile0 * TM_N;
    #pragma unroll 1
    for (int p = 0; p < 4; p++) { ld_pf(w0f + 64 * p); st_pf(p); }
    __syncthreads();

    int rs = 0;
    for (int s = 0; s < ntile; s++) {
        const int w0 = (tile0 + s) * TM_N;
        const bool havepf = (s + 1 < ntile);

        // prefetch next panel (cols w0+256) — LDGs overlap the MMA below
        if (havepf) ld_pf(w0 + 256);

        float acc[2][4][4];
        #pragma unroll
        for (int f = 0; f < 2; f++)
            #pragma unroll
            for (int j = 0; j < 4; j++)
                #pragma unroll
                for (int q = 0; q < 4; q++) acc[f][j][q] = 0.0f;

        #pragma unroll 1
        for (int ks = 0; ks < KS; ks++) {
            const int p = (rs + (ks >> 2)) & 3;
            const uint32_t koff = (uint32_t)(p * A_PANEL_BYTES + ((ks & 3) * 16) * 2);
            uint32_t a0[4], a1[4];
            ldmA(a0, arow0 + koff);
            ldmA(a1, arow1 + koff);
            const uint4* bp = reinterpret_cast<const uint4*>(dsm + OFF_B)
                              + (ks * NCH + ng * 4) * 32 + lane;
            #pragma unroll
            for (int j = 0; j < 4; j++) {
                uint4 bv = bp[j * 32];
                hmma(acc[0][j], a0, bv.x, bv.y);
                hmma(acc[0][j], a0, bv.z, bv.w);
                hmma(acc[1][j], a1, bv.x, bv.y);
                hmma(acc[1][j], a1, bv.z, bv.w);
            }
        }

        // ---- epilogue ----
        #pragma unroll
        for (int f = 0; f < 2; f++) {
            const long long r0 = b0 + m0 + f * 16 + (lane >> 2);
            #pragma unroll
            for (int j = 0; j < 4; j++) {
                int col = w0 + (ng * 4 + j) * 8 + (lane & 3) * 2;
                if (col < t_out) {
                    if (r0 < b_total)
                        *reinterpret_cast<float2*>(out + r0 * t_out + col) =
                            make_float2(acc[f][j][0], acc[f][j][1]);
                    if (r0 + 8 < b_total)
                        *reinterpret_cast<float2*>(out + (r0 + 8) * t_out + col) =
                            make_float2(acc[f][j][2], acc[f][j][3]);
                }
            }
        }

        __syncthreads();                 // all warps done reading panel rs
        if (havepf) st_pf(rs);           // overwrite oldest panel
        rs = (rs + 1) & 3;
        __syncthreads();                 // new panel visible
    }
}

// Generic fallback for unexpected tap counts.
__global__ void fir_generic_kernel(const float* __restrict__ u,
                                   const float* __restrict__ kern,
                                   float* __restrict__ out,
                                   int t_out, int t_in, int kt)
{
    int t = blockIdx.x * blockDim.x + threadIdx.x;
    int row = blockIdx.y;
    if (t >= t_out) return;
    const float* urow = u + (long long)row * t_in;
    float acc = 0.0f;
    for (int i = 0; i < kt; i++)
        acc = fmaf(kern[kt - 1 - i], urow[t + i], acc);
    out[(long long)row * t_out + t] = acc;
}

extern "C" void kernel_launch(void* const* d_in, const int* in_sizes, int n_in,
                              void* d_out, int out_size)
{
    const float* u    = (const float*)d_in[0];
    const float* kern = (const float*)d_in[1];
    float* out        = (float*)d_out;

    const int kt      = in_sizes[1];
    const int b_total = (kt > 1) ? (in_sizes[0] - out_size) / (kt - 1) : 1;
    const int t_out   = out_size / b_total;
    const int t_in    = in_sizes[0] / b_total;

    if (kt >= 1 && kt <= TM_K - TM_N + 1) {
        cudaFuncSetAttribute(fir_hmma_kernel,
                             cudaFuncAttributeMaxDynamicSharedMemorySize, SMEM_TOTAL);
        const int n_btiles = (b_total + TM_M - 1) / TM_M;
        const int n_ttiles = (t_out + TM_N - 1) / TM_N;
        int strips_max = 148 / n_btiles; if (strips_max < 1) strips_max = 1;
        int tps    = (n_ttiles + strips_max - 1) / strips_max;
        int strips = (n_ttiles + tps - 1) / tps;
        dim3 grid(strips, n_btiles);
        fir_hmma_kernel<<<grid, NTH, SMEM_TOTAL>>>(u, kern, out, t_out, t_in,
                                                   b_total, kt, n_ttiles, tps);
    } else {
        dim3 grid((t_out + 255) / 256, b_total);
        fir_generic_kernel<<<grid, 256>>>(u, kern, out, t_out, t_in, kt);
    }
}

// round 14
// speedup vs baseline: 2.4441x; 1.2642x over previous
#include <cuda_runtime.h>
#include <cuda_fp16.h>
#include <cstdint>

// ============================================================================
// Tensor-core FIR via baseline mma.sync (HMMA), software-pipelined, 2 CTA/SM.
// out[b,t] = sum_{i<kt} krev[i]*u[b,t+i],  krev[i] = kern[kt-1-i]
// Per tile: D[128 x 64] = U[128 x 256] * T^T,  T[n,k] = krev[k-n]
// fp16 K-split, 2 passes: U*Kh + U*Kl.
// A: ring of 4 SMEM panels (128 rows x 64 cols fp16, stride 72).
// B: Toeplitz-deduplicated fragments — frag(ks,nc) depends only on
//    d = 2*ks - nc (38 distinct values) -> 19.5 KB instead of 64 KB.
// SMEM ~93 KB  => 2 CTAs/SM (16 warps) for cross-CTA latency hiding.
// ============================================================================

#define TM_M 128
#define TM_N 64
#define TM_K 256
#define NTH  256
#define KS   16
#define NCH  8
#define NDIAG 38                                 // d = 2*ks - nc + 7 in [0,37]

#define A_STRIDE 72                              // 64 + 8 halves pad
#define A_PANEL_BYTES (TM_M * A_STRIDE * 2)      // 18432
#define OFF_A 0
#define OFF_B (4 * A_PANEL_BYTES)                // 73728
#define B_BYTES (NDIAG * 32 * 16)                // 19456
#define SMEM_TOTAL (OFF_B + B_BYTES)             // 93184

__device__ __forceinline__ uint32_t smem_addr(const void* p) {
    uint32_t a;
    asm("{ .reg .u64 t; cvta.to.shared.u64 t, %1; cvt.u32.u64 %0, t; }" : "=r"(a) : "l"(p));
    return a;
}
__device__ __forceinline__ void ldmA(uint32_t* r, uint32_t addr) {
    asm volatile("ldmatrix.sync.aligned.m8n8.x4.shared.b16 {%0,%1,%2,%3}, [%4];"
                 : "=r"(r[0]), "=r"(r[1]), "=r"(r[2]), "=r"(r[3]) : "r"(addr));
}
__device__ __forceinline__ void hmma(float* c, const uint32_t* a, uint32_t b0, uint32_t b1) {
    asm volatile(
        "mma.sync.aligned.m16n8k16.row.col.f32.f16.f16.f32 "
        "{%0,%1,%2,%3}, {%4,%5,%6,%7}, {%8,%9}, {%0,%1,%2,%3};"
        : "+f"(c[0]), "+f"(c[1]), "+f"(c[2]), "+f"(c[3])
        : "r"(a[0]), "r"(a[1]), "r"(a[2]), "r"(a[3]), "r"(b0), "r"(b1));
}
__device__ __forceinline__ uint32_t pkh(__half a, __half b) {
    return (uint32_t)__half_as_ushort(a) | ((uint32_t)__half_as_ushort(b) << 16);
}

__global__ __launch_bounds__(NTH, 2)
void fir_hmma_kernel(const float* __restrict__ u,
                     const float* __restrict__ kern,
                     float* __restrict__ out,
                     int t_out, int t_in, int b_total, int kt,
                     int n_ttiles, int tps)
{
    extern __shared__ char dsm[];
    const uint32_t sbase = smem_addr(dsm);
    const int tid  = threadIdx.x;
    const int wid  = tid >> 5;
    const int lane = tid & 31;
    const long long b0 = (long long)blockIdx.y * TM_M;
    const int tile0 = blockIdx.x * tps;
    const int ntile = min(tps, n_ttiles - tile0);
    const bool al4  = ((t_in & 3) == 0);

    // ---- build deduplicated B fragments (once per CTA) ----
    // fragD[dIdx][lane] 16B: {kh(i0,i0+1), kh(i0+8... )} where for lane l:
    //   i = 8*(dIdx-7) + 2*(l&3) + delta - (l>>2),  delta in {0,1,8,9}
    for (int idx = tid; idx < NDIAG * 32; idx += NTH) {
        int l    = idx & 31;
        int dIdx = idx >> 5;
        int base = 8 * (dIdx - 7) + 2 * (l & 3) - (l >> 2);
        float v[4];
        #pragma unroll
        for (int q = 0; q < 4; q++) {
            int i = base + (q & 1) + ((q >> 1) << 3);   // +0,+1,+8,+9
            v[q] = (i >= 0 && i < kt) ? kern[kt - 1 - i] : 0.0f;
        }
        __half h[4], lo[4];
        #pragma unroll
        for (int q = 0; q < 4; q++) {
            h[q]  = __float2half_rn(v[q]);
            lo[q] = __float2half_rn(v[q] - __half2float(h[q]));
        }
        uint4 w;
        w.x = pkh(h[0],  h[1]);  w.y = pkh(h[2],  h[3]);
        w.z = pkh(lo[0], lo[1]); w.w = pkh(lo[2], lo[3]);
        reinterpret_cast<uint4*>(dsm + OFF_B)[idx] = w;
    }

    // ---- panel staging: 128 rows x 16 float4; 8 float4 per thread ----
    float4 pf[8];
    auto ld_pf = [&](int c0) {
        #pragma unroll
        for (int q = 0; q < 8; q++) {
            int f   = tid + q * NTH;
            int row = f >> 4;
            int cl  = (f & 15) << 2;
            int g   = c0 + cl;
            long long b = b0 + row;
            float4 v = make_float4(0.f, 0.f, 0.f, 0.f);
            if (b < b_total) {
                const float* up = u + b * (long long)t_in + g;
                if (al4 && (g + 3 < t_in)) {
                    v = *(const float4*)up;
                } else {
                    if (g     < t_in) v.x = up[0];
                    if (g + 1 < t_in) v.y = up[1];
                    if (g + 2 < t_in) v.z = up[2];
                    if (g + 3 < t_in) v.w = up[3];
                }
            }
            pf[q] = v;
        }
    };
    auto st_pf = [&](int p) {
        char* pb = dsm + OFF_A + p * A_PANEL_BYTES;
        #pragma unroll
        for (int q = 0; q < 8; q++) {
            int f   = tid + q * NTH;
            int row = f >> 4;
            int cl  = (f & 15) << 2;
            uint2 hv;
            hv.x = pkh(__float2half_rn(pf[q].x), __float2half_rn(pf[q].y));
            hv.y = pkh(__float2half_rn(pf[q].z), __float2half_rn(pf[q].w));
            *reinterpret_cast<uint2*>(pb + (row * A_STRIDE + cl) * 2) = hv;
        }
    };

    // ---- warp tiling: 8 warps, 32 rows x 32 cols each ----
    const int mg  = wid >> 1;          // 0..3 -> rows mg*32
    const int ng  = wid & 1;           // 0..1 -> nc ng*4 + j
    const int m0  = mg * 32;
    const uint32_t arow0 = sbase + OFF_A +
        (uint32_t)(((m0 + (lane & 7) + (lane & 8)) * A_STRIDE + ((lane & 16) ? 8 : 0)) * 2);
    const uint32_t arow1 = arow0 + (uint32_t)(16 * A_STRIDE * 2);

    // ---- initial fill: panels 0..3 ----
    const int w0f = tile0 * TM_N;
    #pragma unroll 1
    for (int p = 0; p < 4; p++) { ld_pf(w0f + 64 * p); st_pf(p); }
    __syncthreads();

    int rs = 0;
    for (int s = 0; s < ntile; s++) {
        const int w0 = (tile0 + s) * TM_N;
        const bool havepf = (s + 1 < ntile);

        if (havepf) ld_pf(w0 + 256);   // LDGs overlap the MMA below

        float acc[2][4][4];
        #pragma unroll
        for (int f = 0; f < 2; f++)
            #pragma unroll
            for (int j = 0; j < 4; j++)
                #pragma unroll
                for (int q = 0; q < 4; q++) acc[f][j][q] = 0.0f;

        #pragma unroll 1
        for (int ks = 0; ks < KS; ks++) {
            const int p = (rs + (ks >> 2)) & 3;
            const uint32_t koff = (uint32_t)(p * A_PANEL_BYTES + ((ks & 3) * 16) * 2);
            uint32_t a0[4], a1[4];
            ldmA(a0, arow0 + koff);
            ldmA(a1, arow1 + koff);
            // frag(ks, nc=ng*4+j) = fragD[2*ks - nc + 7]
            const uint4* bp = reinterpret_cast<const uint4*>(dsm + OFF_B)
                              + (2 * ks - ng * 4 + 7) * 32 + lane;
            #pragma unroll
            for (int j = 0; j < 4; j++) {
                uint4 bv = bp[-j * 32];
                hmma(acc[0][j], a0, bv.x, bv.y);
                hmma(acc[0][j], a0, bv.z, bv.w);
                hmma(acc[1][j], a1, bv.x, bv.y);
                hmma(acc[1][j], a1, bv.z, bv.w);
            }
        }

        // ---- epilogue ----
        #pragma unroll
        for (int f = 0; f < 2; f++) {
            const long long r0 = b0 + m0 + f * 16 + (lane >> 2);
            #pragma unroll
            for (int j = 0; j < 4; j++) {
                int col = w0 + (ng * 4 + j) * 8 + (lane & 3) * 2;
                if (col < t_out) {
                    if (r0 < b_total)
                        *reinterpret_cast<float2*>(out + r0 * t_out + col) =
                            make_float2(acc[f][j][0], acc[f][j][1]);
                    if (r0 + 8 < b_total)
                        *reinterpret_cast<float2*>(out + (r0 + 8) * t_out + col) =
                            make_float2(acc[f][j][2], acc[f][j][3]);
                }
            }
        }

        __syncthreads();                 // all warps done reading panel rs
        if (havepf) st_pf(rs);           // overwrite oldest panel
        rs = (rs + 1) & 3;
        __syncthreads();                 // new panel visible
    }
}

// Generic fallback for unexpected tap counts.
__global__ void fir_generic_kernel(const float* __restrict__ u,
                                   const float* __restrict__ kern,
                                   float* __restrict__ out,
                                   int t_out, int t_in, int kt)
{
    int t = blockIdx.x * blockDim.x + threadIdx.x;
    int row = blockIdx.y;
    if (t >= t_out) return;
    const float* urow = u + (long long)row * t_in;
    float acc = 0.0f;
    for (int i = 0; i < kt; i++)
        acc = fmaf(kern[kt - 1 - i], urow[t + i], acc);
    out[(long long)row * t_out + t] = acc;
}

extern "C" void kernel_launch(void* const* d_in, const int* in_sizes, int n_in,
                              void* d_out, int out_size)
{
    const float* u    = (const float*)d_in[0];
    const float* kern = (const float*)d_in[1];
    float* out        = (float*)d_out;

    const int kt      = in_sizes[1];
    const int b_total = (kt > 1) ? (in_sizes[0] - out_size) / (kt - 1) : 1;
    const int t_out   = out_size / b_total;
    const int t_in    = in_sizes[0] / b_total;

    if (kt >= 1 && kt <= TM_K - TM_N + 1) {
        cudaFuncSetAttribute(fir_hmma_kernel,
                             cudaFuncAttributeMaxDynamicSharedMemorySize, SMEM_TOTAL);
        const int n_btiles = (b_total + TM_M - 1) / TM_M;
        const int n_ttiles = (t_out + TM_N - 1) / TM_N;
        int strips_max = (148 * 2) / n_btiles; if (strips_max < 1) strips_max = 1;
        int tps    = (n_ttiles + strips_max - 1) / strips_max;
        int strips = (n_ttiles + tps - 1) / tps;
        dim3 grid(strips, n_btiles);
        fir_hmma_kernel<<<grid, NTH, SMEM_TOTAL>>>(u, kern, out, t_out, t_in,
                                                   b_total, kt, n_ttiles, tps);
    } else {
        dim3 grid((t_out + 255) / 256, b_total);
        fir_generic_kernel<<<grid, 256>>>(u, kern, out, t_out, t_in, kt);
    }
}

// round 15
// speedup vs baseline: 3.2662x; 1.3363x over previous
#include <cuda_runtime.h>
#include <cuda_fp16.h>
#include <cstdint>

// ============================================================================
// Tensor-core FIR via baseline mma.sync (HMMA), single-pass fp16, 2 CTA/SM.
// out[b,t] = sum_{i<kt} krev[i]*u[b,t+i],  krev[i] = kern[kt-1-i]
// Per tile: D[128 x 64] = U[128 x 256] * T^T,  T[n,k] = krev[k-n]
// Single fp16 pass (U and K rounded to fp16; rel_err ~3e-4 < 1e-3).
// A: ring of 4 SMEM panels (128 rows x 64 cols fp16, stride 72).
// B: Toeplitz-dedup fragments (38 diagonals x 8B), rolling reuse across ks.
// SMEM ~83.5 KB => 2 CTAs/SM for cross-CTA latency hiding.
// ============================================================================

#define TM_M 128
#define TM_N 64
#define TM_K 256
#define NTH  256
#define KS   16
#define NDIAG 38                                 // d = 2*ks - nc + 7 in [0,37]

#define A_STRIDE 72                              // 64 + 8 halves pad
#define A_PANEL_BYTES (TM_M * A_STRIDE * 2)      // 18432
#define OFF_A 0
#define OFF_B (4 * A_PANEL_BYTES)                // 73728
#define B_BYTES (NDIAG * 32 * 8)                 // 9728
#define SMEM_TOTAL (OFF_B + B_BYTES)             // 83456

__device__ __forceinline__ uint32_t smem_addr(const void* p) {
    uint32_t a;
    asm("{ .reg .u64 t; cvta.to.shared.u64 t, %1; cvt.u32.u64 %0, t; }" : "=r"(a) : "l"(p));
    return a;
}
__device__ __forceinline__ void ldmA(uint32_t* r, uint32_t addr) {
    asm volatile("ldmatrix.sync.aligned.m8n8.x4.shared.b16 {%0,%1,%2,%3}, [%4];"
                 : "=r"(r[0]), "=r"(r[1]), "=r"(r[2]), "=r"(r[3]) : "r"(addr));
}
__device__ __forceinline__ void hmma(float* c, const uint32_t* a, uint32_t b0, uint32_t b1) {
    asm volatile(
        "mma.sync.aligned.m16n8k16.row.col.f32.f16.f16.f32 "
        "{%0,%1,%2,%3}, {%4,%5,%6,%7}, {%8,%9}, {%0,%1,%2,%3};"
        : "+f"(c[0]), "+f"(c[1]), "+f"(c[2]), "+f"(c[3])
        : "r"(a[0]), "r"(a[1]), "r"(a[2]), "r"(a[3]), "r"(b0), "r"(b1));
}
__device__ __forceinline__ uint32_t pkh(__half a, __half b) {
    return (uint32_t)__half_as_ushort(a) | ((uint32_t)__half_as_ushort(b) << 16);
}

__global__ __launch_bounds__(NTH, 2)
void fir_hmma_kernel(const float* __restrict__ u,
                     const float* __restrict__ kern,
                     float* __restrict__ out,
                     int t_out, int t_in, int b_total, int kt,
                     int n_ttiles, int tps)
{
    extern __shared__ char dsm[];
    const uint32_t sbase = smem_addr(dsm);
    const int tid  = threadIdx.x;
    const int wid  = tid >> 5;
    const int lane = tid & 31;
    const long long b0 = (long long)blockIdx.y * TM_M;
    const int tile0 = blockIdx.x * tps;
    const int ntile = min(tps, n_ttiles - tile0);
    const bool al4  = ((t_in & 3) == 0);

    // ---- build dedup B fragments (fp16 hi only), once per CTA ----
    // fragD[dIdx][lane] 8B: {kh(i0,i0+1), kh(i0+8,i0+9)},
    //   i0 = 8*(dIdx-7) + 2*(lane&3) - (lane>>2)
    for (int idx = tid; idx < NDIAG * 32; idx += NTH) {
        int l    = idx & 31;
        int dIdx = idx >> 5;
        int base = 8 * (dIdx - 7) + 2 * (l & 3) - (l >> 2);
        __half h[4];
        #pragma unroll
        for (int q = 0; q < 4; q++) {
            int i = base + (q & 1) + ((q >> 1) << 3);   // +0,+1,+8,+9
            float v = (i >= 0 && i < kt) ? kern[kt - 1 - i] : 0.0f;
            h[q] = __float2half_rn(v);
        }
        uint2 w;
        w.x = pkh(h[0], h[1]);
        w.y = pkh(h[2], h[3]);
        reinterpret_cast<uint2*>(dsm + OFF_B)[idx] = w;
    }

    // ---- panel staging: 128 rows x 16 float4; 8 float4 per thread ----
    float4 pf[8];
    auto ld_pf = [&](int c0) {
        #pragma unroll
        for (int q = 0; q < 8; q++) {
            int f   = tid + q * NTH;
            int row = f >> 4;
            int cl  = (f & 15) << 2;
            int g   = c0 + cl;
            long long b = b0 + row;
            float4 v = make_float4(0.f, 0.f, 0.f, 0.f);
            if (b < b_total) {
                const float* up = u + b * (long long)t_in + g;
                if (al4 && (g + 3 < t_in)) {
                    v = *(const float4*)up;
                } else {
                    if (g     < t_in) v.x = up[0];
                    if (g + 1 < t_in) v.y = up[1];
                    if (g + 2 < t_in) v.z = up[2];
                    if (g + 3 < t_in) v.w = up[3];
                }
            }
            pf[q] = v;
        }
    };
    auto st_pf = [&](int p) {
        char* pb = dsm + OFF_A + p * A_PANEL_BYTES;
        #pragma unroll
        for (int q = 0; q < 8; q++) {
            int f   = tid + q * NTH;
            int row = f >> 4;
            int cl  = (f & 15) << 2;
            uint2 hv;
            hv.x = pkh(__float2half_rn(pf[q].x), __float2half_rn(pf[q].y));
            hv.y = pkh(__float2half_rn(pf[q].z), __float2half_rn(pf[q].w));
            *reinterpret_cast<uint2*>(pb + (row * A_STRIDE + cl) * 2) = hv;
        }
    };

    // ---- warp tiling: 8 warps, 32 rows x 32 cols each ----
    const int mg  = wid >> 1;          // 0..3 -> rows mg*32
    const int ng  = wid & 1;           // 0..1 -> nc = ng*4 + j
    const int m0  = mg * 32;
    const uint32_t arow0 = sbase + OFF_A +
        (uint32_t)(((m0 + (lane & 7) + (lane & 8)) * A_STRIDE + ((lane & 16) ? 8 : 0)) * 2);
    const uint32_t arow1 = arow0 + (uint32_t)(16 * A_STRIDE * 2);

    const uint2* __restrict__ bt =
        reinterpret_cast<const uint2*>(dsm + OFF_B);
    const int d00 = 7 - 4 * ng;        // d for (ks=0, j=0)

    // ---- initial fill: panels 0..3 ----
    const int w0f = tile0 * TM_N;
    #pragma unroll 1
    for (int p = 0; p < 4; p++) { ld_pf(w0f + 64 * p); st_pf(p); }
    __syncthreads();

    int rs = 0;
    for (int s = 0; s < ntile; s++) {
        const int w0 = (tile0 + s) * TM_N;
        const bool havepf = (s + 1 < ntile);

        if (havepf) ld_pf(w0 + 256);   // LDGs overlap the MMA below

        float acc[2][4][4];
        #pragma unroll
        for (int f = 0; f < 2; f++)
            #pragma unroll
            for (int j = 0; j < 4; j++)
                #pragma unroll
                for (int q = 0; q < 4; q++) acc[f][j][q] = 0.0f;

        // rolling B fragments: bv[j] = fragD[d00 + 2*ks - j]
        uint2 bv[4];
        #pragma unroll
        for (int j = 0; j < 4; j++) bv[j] = bt[(d00 - j) * 32 + lane];

        #pragma unroll
        for (int ks = 0; ks < KS; ks++) {
            const int p = (rs + (ks >> 2)) & 3;
            const uint32_t koff = (uint32_t)(p * A_PANEL_BYTES + ((ks & 3) * 16) * 2);
            uint32_t a0[4], a1[4];
            ldmA(a0, arow0 + koff);
            ldmA(a1, arow1 + koff);
            #pragma unroll
            for (int j = 0; j < 4; j++) {
                hmma(acc[0][j], a0, bv[j].x, bv[j].y);
                hmma(acc[1][j], a1, bv[j].x, bv[j].y);
            }
            if (ks < KS - 1) {
                // shift: reuse d, d-1 as next j=2,3; load 2 new diagonals
                bv[2] = bv[0];
                bv[3] = bv[1];
                bv[0] = bt[(d00 + 2 * ks + 2) * 32 + lane];
                bv[1] = bt[(d00 + 2 * ks + 1) * 32 + lane];
            }
        }

        // ---- epilogue ----
        #pragma unroll
        for (int f = 0; f < 2; f++) {
            const long long r0 = b0 + m0 + f * 16 + (lane >> 2);
            #pragma unroll
            for (int j = 0; j < 4; j++) {
                int col = w0 + (ng * 4 + j) * 8 + (lane & 3) * 2;
                if (col < t_out) {
                    if (r0 < b_total)
                        *reinterpret_cast<float2*>(out + r0 * t_out + col) =
                            make_float2(acc[f][j][0], acc[f][j][1]);
                    if (r0 + 8 < b_total)
                        *reinterpret_cast<float2*>(out + (r0 + 8) * t_out + col) =
                            make_float2(acc[f][j][2], acc[f][j][3]);
                }
            }
        }

        __syncthreads();                 // all warps done reading panel rs
        if (havepf) st_pf(rs);           // overwrite oldest panel
        rs = (rs + 1) & 3;
        __syncthreads();                 // new panel visible
    }
}

// Generic fallback for unexpected tap counts.
__global__ void fir_generic_kernel(const float* __restrict__ u,
                                   const float* __restrict__ kern,
                                   float* __restrict__ out,
                                   int t_out, int t_in, int kt)
{
    int t = blockIdx.x * blockDim.x + threadIdx.x;
    int row = blockIdx.y;
    if (t >= t_out) return;
    const float* urow = u + (long long)row * t_in;
    float acc = 0.0f;
    for (int i = 0; i < kt; i++)
        acc = fmaf(kern[kt - 1 - i], urow[t + i], acc);
    out[(long long)row * t_out + t] = acc;
}

extern "C" void kernel_launch(void* const* d_in, const int* in_sizes, int n_in,
                              void* d_out, int out_size)
{
    const float* u    = (const float*)d_in[0];
    const float* kern = (const float*)d_in[1];
    float* out        = (float*)d_out;

    const int kt      = in_sizes[1];
    const int b_total = (kt > 1) ? (in_sizes[0] - out_size) / (kt - 1) : 1;
    const int t_out   = out_size / b_total;
    const int t_in    = in_sizes[0] / b_total;

    if (kt >= 1 && kt <= TM_K - TM_N + 1) {
        cudaFuncSetAttribute(fir_hmma_kernel,
                             cudaFuncAttributeMaxDynamicSharedMemorySize, SMEM_TOTAL);
        const int n_btiles = (b_total + TM_M - 1) / TM_M;
        const int n_ttiles = (t_out + TM_N - 1) / TM_N;
        int strips_max = (148 * 2) / n_btiles; if (strips_max < 1) strips_max = 1;
        int tps    = (n_ttiles + strips_max - 1) / strips_max;
        int strips = (n_ttiles + tps - 1) / tps;
        dim3 grid(strips, n_btiles);
        fir_hmma_kernel<<<grid, NTH, SMEM_TOTAL>>>(u, kern, out, t_out, t_in,
                                                   b_total, kt, n_ttiles, tps);
    } else {
        dim3 grid((t_out + 255) / 256, b_total);
        fir_generic_kernel<<<grid, 256>>>(u, kern, out, t_out, t_in, kt);
    }
}